// round 2
// baseline (speedup 1.0000x reference)
#include <cuda_runtime.h>

#define LBL 32
#define BMAX 8

// scratch: per-batch per-label accumulators
// g_acc1: [B][L][5] = {cnt_k, sum_e0..sum_e3}   (kernel-masked segment sums)
// g_acc2: [B][L][2] = {sum_val, cnt}            (aggregation-loss segment sums)
__device__ float g_acc1[BMAX * LBL * 5];
__device__ float g_acc2[BMAX * LBL * 2];

__global__ void k_zero() {
    for (int i = threadIdx.x; i < BMAX * LBL * 5; i += blockDim.x) g_acc1[i] = 0.f;
    for (int i = threadIdx.x; i < BMAX * LBL * 2; i += blockDim.x) g_acc2[i] = 0.f;
}

// Pass 1: per-label kernel-region counts and embedding sums.
__global__ void __launch_bounds__(256) k_pass1(
    const float* __restrict__ emb, const int* __restrict__ inst,
    const float* __restrict__ ker, const float* __restrict__ tmk, int NPIX)
{
    __shared__ float s[LBL * 5];
    const int b = blockIdx.y;
    for (int i = threadIdx.x; i < LBL * 5; i += blockDim.x) s[i] = 0.f;
    __syncthreads();

    const int*   ip = inst + (size_t)b * NPIX;
    const float* kp = ker  + (size_t)b * NPIX;
    const float* mp = tmk  + (size_t)b * NPIX;
    const float* ep = emb  + (size_t)b * 4 * NPIX;

    float zero_cnt = 0.f;  // count of pixels landing in label-0 bucket
    const int stride = gridDim.x * blockDim.x;
    for (int i = blockIdx.x * blockDim.x + threadIdx.x; i < NPIX; i += stride) {
        int   lab = ip[i];
        float tv  = mp[i];
        float kv  = kp[i];
        int labk = (tv > 0.5f && kv > 0.5f) ? lab : 0;
        if (labk > 0) {
            float e0 = ep[i];
            float e1 = ep[i + NPIX];
            float e2 = ep[i + 2 * NPIX];
            float e3 = ep[i + 3 * NPIX];
            float* sp = s + labk * 5;
            atomicAdd(sp + 0, 1.f);
            atomicAdd(sp + 1, e0);
            atomicAdd(sp + 2, e1);
            atomicAdd(sp + 3, e2);
            atomicAdd(sp + 4, e3);
        } else {
            zero_cnt += 1.f;
        }
    }
    // warp-reduce the hot label-0 count instead of hammering one shared address
    for (int o = 16; o; o >>= 1) zero_cnt += __shfl_down_sync(0xffffffffu, zero_cnt, o);
    if ((threadIdx.x & 31) == 0 && zero_cnt != 0.f) atomicAdd(&s[0], zero_cnt);
    __syncthreads();

    for (int i = threadIdx.x; i < LBL * 5; i += blockDim.x)
        if (s[i] != 0.f) atomicAdd(&g_acc1[b * LBL * 5 + i], s[i]);
}

// Pass 2: per-pixel distance to own label's kernel mean; segment sums of log-val.
__global__ void __launch_bounds__(256) k_pass2(
    const float* __restrict__ emb, const int* __restrict__ inst,
    const float* __restrict__ tmk, int NPIX)
{
    __shared__ float mean[LBL][4];
    __shared__ float s[LBL * 2];
    const int b = blockIdx.y;

    // each block recomputes emb_mean from g_acc1 (160 floats, L2-resident)
    if (threadIdx.x < LBL * 4) {
        int l = threadIdx.x >> 2, d = threadIdx.x & 3;
        float c = g_acc1[(b * LBL + l) * 5];
        mean[l][d] = (l == 0) ? 0.f
                             : g_acc1[(b * LBL + l) * 5 + 1 + d] / fmaxf(c, 1.f);
    }
    for (int i = threadIdx.x; i < LBL * 2; i += blockDim.x) s[i] = 0.f;
    __syncthreads();

    const int*   ip = inst + (size_t)b * NPIX;
    const float* mp = tmk  + (size_t)b * NPIX;
    const float* ep = emb  + (size_t)b * 4 * NPIX;

    const int stride = gridDim.x * blockDim.x;
    for (int i = blockIdx.x * blockDim.x + threadIdx.x; i < NPIX; i += stride) {
        int   lab = ip[i];
        float tv  = mp[i];
        int labm = (tv > 0.5f) ? lab : 0;
        if (labm > 0) {
            float d0 = ep[i]            - mean[labm][0];
            float d1 = ep[i + NPIX]     - mean[labm][1];
            float d2 = ep[i + 2 * NPIX] - mean[labm][2];
            float d3 = ep[i + 3 * NPIX] - mean[labm][3];
            float sq = d0 * d0 + d1 * d1 + d2 * d2 + d3 * d3;
            float dist = (sq > 0.f) ? sqrtf(sq) : 0.f;
            float r = fmaxf(dist - 0.5f, 0.f);      // DELTA_AGG = 0.5
            float val = log1pf(r * r);
            atomicAdd(&s[labm * 2 + 0], val);
            atomicAdd(&s[labm * 2 + 1], 1.f);
        }
    }
    __syncthreads();

    for (int i = threadIdx.x; i < LBL * 2; i += blockDim.x)
        if (s[i] != 0.f) atomicAdd(&g_acc2[b * LBL * 2 + i], s[i]);
}

// Finalize: per batch, one warp. agg + discrimination + regularizer.
__global__ void k_final(float* __restrict__ out) {
    const int b = blockIdx.x;
    const int l = threadIdx.x;  // 0..31

    float c = g_acc1[(b * LBL + l) * 5];
    float m0 = 0.f, m1 = 0.f, m2 = 0.f, m3 = 0.f;
    if (l > 0) {
        float inv = 1.f / fmaxf(c, 1.f);
        m0 = g_acc1[(b * LBL + l) * 5 + 1] * inv;
        m1 = g_acc1[(b * LBL + l) * 5 + 2] * inv;
        m2 = g_acc1[(b * LBL + l) * 5 + 3] * inv;
        m3 = g_acc1[(b * LBL + l) * 5 + 4] * inv;
    }
    bool present = (c > 0.f);
    unsigned pb = __ballot_sync(0xffffffffu, present);
    int ni = __popc(pb);                 // num_instance (includes label 0)
    unsigned nzb = pb & ~1u;             // present labels > 0
    bool nz = present && (l > 0);

    __shared__ float sm[LBL][4];
    sm[l][0] = m0; sm[l][1] = m1; sm[l][2] = m2; sm[l][3] = m3;
    __syncwarp();

    // aggregation term
    float sv = g_acc2[(b * LBL + l) * 2 + 0];
    float ct = g_acc2[(b * LBL + l) * 2 + 1];
    float aggl = nz ? sv / fmaxf(ct, 1.f) : 0.f;

    // regularizer term
    float sq = m0 * m0 + m1 * m1 + m2 * m2 + m3 * m3;
    float nrm = (sq > 0.f) ? sqrtf(sq) : 0.f;
    float reg = present ? log1pf(nrm) : 0.f;

    // discrimination term (all ordered pairs of distinct present nz labels)
    float ds = 0.f, dc = 0.f;
    if (nz) {
        #pragma unroll
        for (int j = 1; j < LBL; j++) {
            if (j != l && ((nzb >> j) & 1u)) {
                float p0 = m0 - sm[j][0];
                float p1 = m1 - sm[j][1];
                float p2 = m2 - sm[j][2];
                float p3 = m3 - sm[j][3];
                float psq = p0 * p0 + p1 * p1 + p2 * p2 + p3 * p3;
                float pd = (psq > 0.f) ? sqrtf(psq) : 0.f;
                float r = fmaxf(3.0f - pd, 0.f);    // 2 * DELTA_DIS = 3.0
                ds += log1pf(r * r);
                dc += 1.f;
            }
        }
    }
    // warp reductions
    for (int o = 16; o; o >>= 1) {
        aggl += __shfl_down_sync(0xffffffffu, aggl, o);
        reg  += __shfl_down_sync(0xffffffffu, reg,  o);
        ds   += __shfl_down_sync(0xffffffffu, ds,   o);
        dc   += __shfl_down_sync(0xffffffffu, dc,   o);
    }
    if (l == 0) {
        float l_agg = aggl / (float)((ni - 1) > 1 ? (ni - 1) : 1);
        float l_reg = reg / (float)(ni > 1 ? ni : 1) * 0.001f;   // REG_W
        float l_dis = (ni > 2) ? ds / fmaxf(dc, 1.f) : 0.f;
        float loss = l_agg + l_dis + l_reg;
        out[b] = (ni <= 1) ? 0.f : loss;
    }
}

extern "C" void kernel_launch(void* const* d_in, const int* in_sizes, int n_in,
                              void* d_out, int out_size) {
    const float* emb  = (const float*)d_in[0];
    const int*   inst = (const int*)  d_in[1];
    const float* ker  = (const float*)d_in[2];
    const float* tmk  = (const float*)d_in[3];
    float* out = (float*)d_out;

    int B = out_size;                 // 8
    if (B > BMAX) B = BMAX;
    int NPIX = in_sizes[1] / B;       // 736*736 = 541696

    k_zero<<<1, 512>>>();
    dim3 grid(264, B);
    k_pass1<<<grid, 256>>>(emb, inst, ker, tmk, NPIX);
    k_pass2<<<grid, 256>>>(emb, inst, tmk, NPIX);
    k_final<<<B, 32>>>(out);
}